// round 7
// baseline (speedup 1.0000x reference)
#include <cuda_runtime.h>

// Problem sizes (fixed by the reference)
#define BB 32
#define TT 512
#define EE 1024
#define HH 1024

// ---------------------------------------------------------------------------
// f32x2 packed-FMA helpers (sm_103a FFMA2 path; ptxas only emits via PTX)
// ---------------------------------------------------------------------------
static __device__ __forceinline__ void fma2(unsigned long long &acc,
                                            unsigned long long a,
                                            unsigned long long b) {
    asm("fma.rn.f32x2 %0, %1, %2, %0;" : "+l"(acc) : "l"(a), "l"(b));
}
static __device__ __forceinline__ float2 unpk(unsigned long long v) {
    float2 r;
    asm("mov.b64 {%0, %1}, %2;" : "=f"(r.x), "=f"(r.y) : "l"(v));
    return r;
}
static __device__ __forceinline__ unsigned ld_acq(const unsigned* p) {
    unsigned v;
    asm volatile("ld.acquire.gpu.u32 %0, [%1];" : "=r"(v) : "l"(p));
    return v;
}
static __device__ __forceinline__ void st_rel(unsigned* p, unsigned v) {
    asm volatile("st.release.gpu.u32 [%0], %1;" :: "l"(p), "r"(v) : "memory");
}

// ---------------------------------------------------------------------------
// Global scratch: 3-deep hidden-state ring + per-CTA monotonic step flags
// ---------------------------------------------------------------------------
__device__ float    g_h[3][BB * HH];
__device__ unsigned g_flag[128 * 32];       // one flag per CTA, 128B stride

// ---------------------------------------------------------------------------
// Phase 1: out[m][n] = sum_k X[m][k] * W[n][k] + (bih[n] + bhh[n])
// M=16384, N=1024, K=1024, NT GEMM, FFMA2, 128x64 tile, double-buffered smem.
// Block (0,0) additionally zeroes g_h[0] and the flags (init merged here so
// the launch period is 2 kernels -> ncu's sample position hits rnn_rec).
// ---------------------------------------------------------------------------
#define BM  128
#define BN  64
#define BK  32
#define LDA 36

__global__ __launch_bounds__(256) void gemm_xp_kernel(
    const float* __restrict__ X, const float* __restrict__ W,
    const float* __restrict__ bih, const float* __restrict__ bhh,
    float* __restrict__ out)
{
    __shared__ __align__(16) float As[2][BM * LDA];
    __shared__ __align__(16) float Bs[2][BN * LDA];

    const int tid = threadIdx.x;
    const int m0  = blockIdx.y * BM;
    const int n0  = blockIdx.x * BN;
    const int r   = tid & 15;
    const int c   = tid >> 4;

    // ---- merged init (block (0,0) only): zero h_0 ring slot + flags ------
    if (blockIdx.x == 0 && blockIdx.y == 0) {
        float4 z4 = make_float4(0.f, 0.f, 0.f, 0.f);
#pragma unroll
        for (int u = 0; u < 32; u++)                    // 32K floats = 8K f4
            *((float4*)g_h[0] + tid + u * 256) = z4;
#pragma unroll
        for (int u = 0; u < 16; u++)                    // 4096 flags
            g_flag[tid + u * 256] = 0u;
    }

    // staging coordinates (same for every tile)
    const int srow = tid >> 3;
    const int skk  = (tid & 7) << 2;

    unsigned long long acc[8][4];
#pragma unroll
    for (int i = 0; i < 8; i++)
#pragma unroll
        for (int j = 0; j < 4; j++) acc[i][j] = 0ull;

    // Preload tile 0
#pragma unroll
    for (int u = 0; u < 4; u++)
        *(float4*)&As[0][(srow + u * 32) * LDA + skk] =
            *(const float4*)&X[(m0 + srow + u * 32) * EE + skk];
#pragma unroll
    for (int u = 0; u < 2; u++)
        *(float4*)&Bs[0][(srow + u * 32) * LDA + skk] =
            *(const float4*)&W[(n0 + srow + u * 32) * EE + skk];
    __syncthreads();

    int cur = 0;
    for (int kt = 0; kt < EE; kt += BK) {
        // Prefetch next tile into registers (latency hidden under compute)
        float4 pa[4], pb[2];
        if (kt + BK < EE) {
#pragma unroll
            for (int u = 0; u < 4; u++)
                pa[u] = *(const float4*)&X[(m0 + srow + u * 32) * EE + kt + BK + skk];
#pragma unroll
            for (int u = 0; u < 2; u++)
                pb[u] = *(const float4*)&W[(n0 + srow + u * 32) * EE + kt + BK + skk];
        }

#pragma unroll
        for (int kk = 0; kk < BK; kk += 4) {
            ulonglong2 av[8];
            ulonglong2 bv[4];
#pragma unroll
            for (int i = 0; i < 8; i++)
                av[i] = *(const ulonglong2*)&As[cur][(r + 16 * i) * LDA + kk];
#pragma unroll
            for (int j = 0; j < 4; j++)
                bv[j] = *(const ulonglong2*)&Bs[cur][(c + 16 * j) * LDA + kk];
#pragma unroll
            for (int i = 0; i < 8; i++) {
#pragma unroll
                for (int j = 0; j < 4; j++) {
                    fma2(acc[i][j], av[i].x, bv[j].x);
                    fma2(acc[i][j], av[i].y, bv[j].y);
                }
            }
        }

        if (kt + BK < EE) {
#pragma unroll
            for (int u = 0; u < 4; u++)
                *(float4*)&As[1 - cur][(srow + u * 32) * LDA + skk] = pa[u];
#pragma unroll
            for (int u = 0; u < 2; u++)
                *(float4*)&Bs[1 - cur][(srow + u * 32) * LDA + skk] = pb[u];
        }
        __syncthreads();
        cur ^= 1;
    }

#pragma unroll
    for (int j = 0; j < 4; j++) {
        int n = n0 + c + 16 * j;
        float bias = bih[n] + bhh[n];
#pragma unroll
        for (int i = 0; i < 8; i++) {
            float2 v = unpk(acc[i][j]);
            out[(m0 + r + 16 * i) * HH + n] = v.x + v.y + bias;
        }
    }
}

// ---------------------------------------------------------------------------
// Phase 2: persistent recurrence. 128 CTAs (co-resident), 256 threads.
//   CTA = batch group gb (8 batches) x col block cb (32 cols), full K = 1024.
//   Thread (c2 = tid&7, ks = tid>>3) computes an 8x4xKt=32 FFMA2 partial;
//   KS=32 partials reduced via a 32 KB smem tile.
//
//   Sync: per-producer monotonic flags (release/acquire), 3-deep h ring.
//   Fine-grained: the 8 threads {8*ks + c2} stage chunk ks and are its only
//   consumers; lane c2==0 polls the producer flag (spin+nanosleep backoff),
//   then the group syncwarps, stages, and computes — no global barrier
//   between stage and compute.
// ---------------------------------------------------------------------------
#define RGRID   128
#define RW_FLT  (32 * 1024)   // W slice, swizzled     (128 KB)
#define RH_FLT  (8 * 1024)    // h slice, swizzled     ( 32 KB)
#define RR_FLT  (32 * 256)    // reduction partials    ( 32 KB)
#define RSM_BYTES ((RW_FLT + RH_FLT + RR_FLT) * 4)

__global__ __launch_bounds__(256, 1) void rnn_rec_kernel(
    const float* __restrict__ Whh, float* __restrict__ out)
{
    extern __shared__ __align__(16) float sm[];
    float* Ws  = sm;                     // [32 cols][1024] swizzled
    float* hs  = sm + RW_FLT;            // [8 batches][1024] swizzled
    float* red = sm + RW_FLT + RH_FLT;   // [32 ks][256 outputs]

    const int tid = threadIdx.x;
    const int gb  = blockIdx.x >> 5;          // batch group 0..3
    const int c0  = (blockIdx.x & 31) * 32;   // global col base
    const int c2  = tid & 7;                  // col quad 0..7
    const int ks  = tid >> 3;                 // k chunk 0..31

    // ---- Stage W slice (once), applying the W swizzle -------------------
#pragma unroll 4
    for (int u = 0; u < 32; u++) {
        int f   = tid + u * 256;          // float4 index 0..8191
        int col = f >> 8;                 // local col 0..31
        int g   = f & 255;                // granule
        int gp  = (g & ~7) | ((g ^ (g >> 3) ^ col) & 7);
        float4 v = *(const float4*)&Whh[(c0 + col) * HH + g * 4];
        *(float4*)&Ws[col * 1024 + gp * 4] = v;
    }

    // Per-thread invariant offsets
    const int kbase = ks * 32;            // float offset of this k chunk
    const int sxh   = ks & 7;             // h swizzle term
    int sxj[4];
    const float* wb[4];
#pragma unroll
    for (int j = 0; j < 4; j++) {
        int col = c2 * 4 + j;
        sxj[j] = (ks ^ col) & 7;
        wb[j]  = &Ws[col * 1024 + kbase];
    }
    const float* hb = &hs[kbase];

    // Staging: thread tid copies granule tid (chunk ks = tid>>3), whose sole
    // producer is CTA (gb, ks). 8-lane consumer group = threads 8ks..8ks+7.
    const unsigned* my_src_flag = &g_flag[(gb * 32 + ks) * 32];
    unsigned*       my_flag     = &g_flag[blockIdx.x * 32];
    const int g_st  = tid;
    const int gp_st = (g_st & ~7) | ((g_st ^ (g_st >> 3)) & 7);
    const unsigned grp_mask = 0xFFu << (((tid >> 3) & 3) * 8);

    // Epilogue output mapping: o = tid = b*32 + colL (coalesced)
    const int b_out   = tid >> 5;
    const int colL    = tid & 31;
    const int oi_base = (gb * 8 + b_out) * TT * HH + (c0 + colL);
    const int hw_idx  = (gb * 8 + b_out) * HH + (c0 + colL);

    int cur = 0, nxt = 1, nnx = 2;        // rotating ring indices
    float xp_cur = __ldg(&out[oi_base]);  // prefetch xp for t = 0

    __syncthreads();   // Ws fully staged before first microloop

    for (int t = 0; t < TT; t++) {
        // ---- Lane c2==0 polls this chunk's producer (backoff), group sync
        if (t) {
            if (c2 == 0) {
                int spins = 0;
                while (ld_acq(my_src_flag) < (unsigned)t) {
                    if (++spins > 2) __nanosleep(40);
                }
            }
            __syncwarp(grp_mask);
        }
        // ---- Stage 8 granules of this chunk ------------------------------
        {
            const float4* hsrc =
                (const float4*)(g_h[cur] + gb * 8 * HH) + g_st;
            float4* hdst = (float4*)&hs[gp_st * 4];
#pragma unroll
            for (int u = 0; u < 8; u++) {
                float4 v = __ldcg(hsrc + u * 256);
                *(float4*)((char*)hdst + u * 4096) = v;
            }
        }
        __syncwarp(grp_mask);

        // ---- 8x4 x Kt=32 FFMA2 microtile --------------------------------
        unsigned long long acc[8][4];
#pragma unroll
        for (int i = 0; i < 8; i++)
#pragma unroll
            for (int j = 0; j < 4; j++) acc[i][j] = 0ull;

#pragma unroll
        for (int kq = 0; kq < 8; kq++) {
            ulonglong2 hv[8];
            ulonglong2 wv[4];
            int ho = ((kq ^ sxh) & 7) * 4;
#pragma unroll
            for (int i = 0; i < 8; i++)
                hv[i] = *(const ulonglong2*)(hb + i * 1024 + ho);
#pragma unroll
            for (int j = 0; j < 4; j++)
                wv[j] = *(const ulonglong2*)(wb[j] + ((kq ^ sxj[j]) & 7) * 4);
#pragma unroll
            for (int i = 0; i < 8; i++) {
#pragma unroll
                for (int j = 0; j < 4; j++) {
                    fma2(acc[i][j], hv[i].x, wv[j].x);
                    fma2(acc[i][j], hv[i].y, wv[j].y);
                }
            }
        }

        // ---- Reduce KS=32 partials through smem -------------------------
#pragma unroll
        for (int i = 0; i < 8; i++) {
            float2 a0 = unpk(acc[i][0]), a1 = unpk(acc[i][1]);
            float2 a2 = unpk(acc[i][2]), a3 = unpk(acc[i][3]);
            float4 v;
            v.x = a0.x + a0.y; v.y = a1.x + a1.y;
            v.z = a2.x + a2.y; v.w = a3.x + a3.y;
            *(float4*)&red[ks * 256 + i * 32 + c2 * 4] = v;
        }
        __syncthreads();

        float s0 = 0.f, s1 = 0.f, s2 = 0.f, s3 = 0.f;
#pragma unroll
        for (int k = 0; k < 32; k += 4) {
            s0 += red[(k + 0) * 256 + tid];
            s1 += red[(k + 1) * 256 + tid];
            s2 += red[(k + 2) * 256 + tid];
            s3 += red[(k + 3) * 256 + tid];
        }
        float s = (s0 + s1) + (s2 + s3);

        // ---- tanh, publish h, release flag ------------------------------
        float hnew = tanhf(xp_cur + s);
        g_h[nxt][hw_idx] = hnew;
        __syncthreads();                 // all h-writes of this CTA done
        if (tid == 0) st_rel(my_flag, (unsigned)(t + 1));

        // off the critical path:
        out[oi_base + t * HH] = hnew;
        if (t + 1 < TT) xp_cur = __ldg(&out[oi_base + (t + 1) * HH]);

        int tmp = cur; cur = nxt; nxt = nnx; nnx = tmp;
    }
}

// ---------------------------------------------------------------------------
// Launch: input-projection GEMM (+ merged init) -> recurrence  (2 launches)
// ---------------------------------------------------------------------------
extern "C" void kernel_launch(void* const* d_in, const int* in_sizes, int n_in,
                              void* d_out, int out_size)
{
    const float* x   = (const float*)d_in[0];
    const float* Wih = (const float*)d_in[1];
    const float* Whh = (const float*)d_in[2];
    const float* bih = (const float*)d_in[3];
    const float* bhh = (const float*)d_in[4];
    float* out = (float*)d_out;
    (void)in_sizes; (void)n_in; (void)out_size;

    cudaFuncSetAttribute(rnn_rec_kernel,
                         cudaFuncAttributeMaxDynamicSharedMemorySize,
                         RSM_BYTES);

    dim3 g1(HH / BN, (BB * TT) / BM);   // (16, 128)
    gemm_xp_kernel<<<g1, 256>>>(x, Wih, bih, bhh, out);

    rnn_rec_kernel<<<RGRID, 256, RSM_BYTES>>>(Whh, out);
}

// round 8
// speedup vs baseline: 1.1901x; 1.1901x over previous
#include <cuda_runtime.h>

// Problem sizes (fixed by the reference)
#define BB 32
#define TT 512
#define EE 1024
#define HH 1024

// ---------------------------------------------------------------------------
// f32x2 packed-FMA helpers (sm_103a FFMA2 path; ptxas only emits via PTX)
// ---------------------------------------------------------------------------
static __device__ __forceinline__ void fma2(unsigned long long &acc,
                                            unsigned long long a,
                                            unsigned long long b) {
    asm("fma.rn.f32x2 %0, %1, %2, %0;" : "+l"(acc) : "l"(a), "l"(b));
}
static __device__ __forceinline__ float2 unpk(unsigned long long v) {
    float2 r;
    asm("mov.b64 {%0, %1}, %2;" : "=f"(r.x), "=f"(r.y) : "l"(v));
    return r;
}
static __device__ __forceinline__ unsigned ld_acq(const unsigned* p) {
    unsigned v;
    asm volatile("ld.acquire.gpu.u32 %0, [%1];" : "=r"(v) : "l"(p));
    return v;
}
static __device__ __forceinline__ void st_rel(unsigned* p, unsigned v) {
    asm volatile("st.release.gpu.u32 [%0], %1;" :: "l"(p), "r"(v) : "memory");
}
static __device__ __forceinline__ float tanh_fast(float x) {
    float y;
    asm("tanh.approx.f32 %0, %1;" : "=f"(y) : "f"(x));
    return y;
}

// ---------------------------------------------------------------------------
// Global scratch: 3-deep hidden-state ring + per-CTA monotonic step flags
// ---------------------------------------------------------------------------
__device__ float    g_h[3][BB * HH];
__device__ unsigned g_flag[128 * 32];       // one flag per CTA, 128B stride

// ---------------------------------------------------------------------------
// Phase 1: out[m][n] = sum_k X[m][k] * W[n][k] + (bih[n] + bhh[n])
// M=16384, N=1024, K=1024, NT GEMM, FFMA2, 128x64 tile, double-buffered smem.
// Block (0,0) additionally zeroes g_h[0] and the flags (init merged here).
// ---------------------------------------------------------------------------
#define BM  128
#define BN  64
#define BK  32
#define LDA 36

__global__ __launch_bounds__(256) void gemm_xp_kernel(
    const float* __restrict__ X, const float* __restrict__ W,
    const float* __restrict__ bih, const float* __restrict__ bhh,
    float* __restrict__ out)
{
    __shared__ __align__(16) float As[2][BM * LDA];
    __shared__ __align__(16) float Bs[2][BN * LDA];

    const int tid = threadIdx.x;
    const int m0  = blockIdx.y * BM;
    const int n0  = blockIdx.x * BN;
    const int r   = tid & 15;
    const int c   = tid >> 4;

    // ---- merged init (block (0,0) only): zero h_0 ring slot + flags ------
    if (blockIdx.x == 0 && blockIdx.y == 0) {
        float4 z4 = make_float4(0.f, 0.f, 0.f, 0.f);
#pragma unroll
        for (int u = 0; u < 32; u++)                    // 32K floats = 8K f4
            *((float4*)g_h[0] + tid + u * 256) = z4;
#pragma unroll
        for (int u = 0; u < 16; u++)                    // 4096 flags
            g_flag[tid + u * 256] = 0u;
    }

    // staging coordinates (same for every tile)
    const int srow = tid >> 3;
    const int skk  = (tid & 7) << 2;

    unsigned long long acc[8][4];
#pragma unroll
    for (int i = 0; i < 8; i++)
#pragma unroll
        for (int j = 0; j < 4; j++) acc[i][j] = 0ull;

    // Preload tile 0
#pragma unroll
    for (int u = 0; u < 4; u++)
        *(float4*)&As[0][(srow + u * 32) * LDA + skk] =
            *(const float4*)&X[(m0 + srow + u * 32) * EE + skk];
#pragma unroll
    for (int u = 0; u < 2; u++)
        *(float4*)&Bs[0][(srow + u * 32) * LDA + skk] =
            *(const float4*)&W[(n0 + srow + u * 32) * EE + skk];
    __syncthreads();

    int cur = 0;
    for (int kt = 0; kt < EE; kt += BK) {
        float4 pa[4], pb[2];
        if (kt + BK < EE) {
#pragma unroll
            for (int u = 0; u < 4; u++)
                pa[u] = *(const float4*)&X[(m0 + srow + u * 32) * EE + kt + BK + skk];
#pragma unroll
            for (int u = 0; u < 2; u++)
                pb[u] = *(const float4*)&W[(n0 + srow + u * 32) * EE + kt + BK + skk];
        }

#pragma unroll
        for (int kk = 0; kk < BK; kk += 4) {
            ulonglong2 av[8];
            ulonglong2 bv[4];
#pragma unroll
            for (int i = 0; i < 8; i++)
                av[i] = *(const ulonglong2*)&As[cur][(r + 16 * i) * LDA + kk];
#pragma unroll
            for (int j = 0; j < 4; j++)
                bv[j] = *(const ulonglong2*)&Bs[cur][(c + 16 * j) * LDA + kk];
#pragma unroll
            for (int i = 0; i < 8; i++) {
#pragma unroll
                for (int j = 0; j < 4; j++) {
                    fma2(acc[i][j], av[i].x, bv[j].x);
                    fma2(acc[i][j], av[i].y, bv[j].y);
                }
            }
        }

        if (kt + BK < EE) {
#pragma unroll
            for (int u = 0; u < 4; u++)
                *(float4*)&As[1 - cur][(srow + u * 32) * LDA + skk] = pa[u];
#pragma unroll
            for (int u = 0; u < 2; u++)
                *(float4*)&Bs[1 - cur][(srow + u * 32) * LDA + skk] = pb[u];
        }
        __syncthreads();
        cur ^= 1;
    }

#pragma unroll
    for (int j = 0; j < 4; j++) {
        int n = n0 + c + 16 * j;
        float bias = bih[n] + bhh[n];
#pragma unroll
        for (int i = 0; i < 8; i++) {
            float2 v = unpk(acc[i][j]);
            out[(m0 + r + 16 * i) * HH + n] = v.x + v.y + bias;
        }
    }
}

// ---------------------------------------------------------------------------
// Phase 2: persistent recurrence. 128 CTAs (co-resident), 256 threads.
//   CTA = batch group gb (8 batches) x col block cb (32 cols), full K = 1024.
//   Thread (c2 = tid&7, ks = tid>>3) computes an 8x4xKt=32 FFMA2 partial;
//   KS=32 partials reduced via a 32 KB smem tile.
//
//   Swizzle (16B granule, logical gL = ks*8 + kq within a 1024-float row):
//     W store: gp = (gL&~7) | ((gL ^ (gL>>3) ^ (col>>2)) & 7)
//       -> load offset low3 = (kq ^ ks ^ c2): within any 8-lane phase
//          (fixed ks, c2 = 0..7) all 8 bank-groups hit -> CONFLICT-FREE.
//          (R7's col-based term collapsed to 2 groups -> 4-way conflict;
//           that was the measured L1=55% bottleneck.)
//     h store: gp = (gL&~7) | ((gL ^ (gL>>3)) & 7) -> phase-wide broadcast.
// ---------------------------------------------------------------------------
#define RGRID   128
#define RW_FLT  (32 * 1024)   // W slice, swizzled     (128 KB)
#define RH_FLT  (8 * 1024)    // h slice, swizzled     ( 32 KB)
#define RR_FLT  (32 * 256)    // reduction partials    ( 32 KB)
#define RSM_BYTES ((RW_FLT + RH_FLT + RR_FLT) * 4)

__global__ __launch_bounds__(256, 1) void rnn_rec_kernel(
    const float* __restrict__ Whh, float* __restrict__ out)
{
    extern __shared__ __align__(16) float sm[];
    float* Ws  = sm;                     // [32 cols][1024] swizzled
    float* hs  = sm + RW_FLT;            // [8 batches][1024] swizzled
    float* red = sm + RW_FLT + RH_FLT;   // [32 ks][256 outputs]

    const int tid = threadIdx.x;
    const int gb  = blockIdx.x >> 5;          // batch group 0..3
    const int c0  = (blockIdx.x & 31) * 32;   // global col base
    const int c2  = tid & 7;                  // col quad 0..7
    const int ks  = tid >> 3;                 // k chunk 0..31

    // ---- Stage W slice (once), applying the quad-based W swizzle --------
#pragma unroll 4
    for (int u = 0; u < 32; u++) {
        int f   = tid + u * 256;          // float4 index 0..8191
        int col = f >> 8;                 // local col 0..31
        int g   = f & 255;                // granule
        int gp  = (g & ~7) | ((g ^ (g >> 3) ^ (col >> 2)) & 7);
        float4 v = *(const float4*)&Whh[(c0 + col) * HH + g * 4];
        *(float4*)&Ws[col * 1024 + gp * 4] = v;
    }

    // Per-thread invariant offsets
    const int kbase = ks * 32;            // float offset of this k chunk
    const int sxh   = ks & 7;             // h swizzle term
    const int sxw   = (ks ^ c2) & 7;      // W swizzle term (same for all j)
    const float* wb[4];
#pragma unroll
    for (int j = 0; j < 4; j++)
        wb[j] = &Ws[(c2 * 4 + j) * 1024 + kbase];
    const float* hb = &hs[kbase];

    // Staging: thread tid copies granule tid (chunk ks = tid>>3), whose sole
    // producer is CTA (gb, ks). 8-lane consumer group = threads 8ks..8ks+7.
    const unsigned* my_src_flag = &g_flag[(gb * 32 + ks) * 32];
    unsigned*       my_flag     = &g_flag[blockIdx.x * 32];
    const int g_st  = tid;
    const int gp_st = (g_st & ~7) | ((g_st ^ (g_st >> 3)) & 7);
    const unsigned grp_mask = 0xFFu << (((tid >> 3) & 3) * 8);

    // Epilogue output mapping: o = tid = b*32 + colL (coalesced)
    const int b_out   = tid >> 5;
    const int colL    = tid & 31;
    const int oi_base = (gb * 8 + b_out) * TT * HH + (c0 + colL);
    const int hw_idx  = (gb * 8 + b_out) * HH + (c0 + colL);

    int cur = 0, nxt = 1, nnx = 2;        // rotating ring indices
    float xp_cur = __ldg(&out[oi_base]);  // prefetch xp for t = 0

    __syncthreads();   // Ws fully staged before first microloop

    for (int t = 0; t < TT; t++) {
        // ---- Lane c2==0 polls this chunk's producer (backoff), group sync
        if (t) {
            if (c2 == 0) {
                int spins = 0;
                while (ld_acq(my_src_flag) < (unsigned)t) {
                    if (++spins > 2) __nanosleep(20);
                }
            }
            __syncwarp(grp_mask);
        }
        // ---- Stage 8 granules of this chunk ------------------------------
        {
            const float4* hsrc =
                (const float4*)(g_h[cur] + gb * 8 * HH) + g_st;
            float4* hdst = (float4*)&hs[gp_st * 4];
#pragma unroll
            for (int u = 0; u < 8; u++) {
                float4 v = __ldcg(hsrc + u * 256);
                *(float4*)((char*)hdst + u * 4096) = v;
            }
        }
        __syncwarp(grp_mask);

        // ---- 8x4 x Kt=32 FFMA2 microtile --------------------------------
        unsigned long long acc[8][4];
#pragma unroll
        for (int i = 0; i < 8; i++)
#pragma unroll
            for (int j = 0; j < 4; j++) acc[i][j] = 0ull;

#pragma unroll
        for (int kq = 0; kq < 8; kq++) {
            ulonglong2 hv[8];
            ulonglong2 wv[4];
            int ho = ((kq ^ sxh) & 7) * 4;
            int wo = ((kq ^ sxw) & 7) * 4;
#pragma unroll
            for (int i = 0; i < 8; i++)
                hv[i] = *(const ulonglong2*)(hb + i * 1024 + ho);
#pragma unroll
            for (int j = 0; j < 4; j++)
                wv[j] = *(const ulonglong2*)(wb[j] + wo);
#pragma unroll
            for (int i = 0; i < 8; i++) {
#pragma unroll
                for (int j = 0; j < 4; j++) {
                    fma2(acc[i][j], hv[i].x, wv[j].x);
                    fma2(acc[i][j], hv[i].y, wv[j].y);
                }
            }
        }

        // ---- Reduce KS=32 partials through smem -------------------------
#pragma unroll
        for (int i = 0; i < 8; i++) {
            float2 a0 = unpk(acc[i][0]), a1 = unpk(acc[i][1]);
            float2 a2 = unpk(acc[i][2]), a3 = unpk(acc[i][3]);
            float4 v;
            v.x = a0.x + a0.y; v.y = a1.x + a1.y;
            v.z = a2.x + a2.y; v.w = a3.x + a3.y;
            *(float4*)&red[ks * 256 + i * 32 + c2 * 4] = v;
        }
        __syncthreads();

        float s0 = 0.f, s1 = 0.f, s2 = 0.f, s3 = 0.f;
#pragma unroll
        for (int k = 0; k < 32; k += 4) {
            s0 += red[(k + 0) * 256 + tid];
            s1 += red[(k + 1) * 256 + tid];
            s2 += red[(k + 2) * 256 + tid];
            s3 += red[(k + 3) * 256 + tid];
        }
        float s = (s0 + s1) + (s2 + s3);

        // ---- tanh, publish h, release flag ------------------------------
        float hnew = tanh_fast(xp_cur + s);
        g_h[nxt][hw_idx] = hnew;
        __syncthreads();                 // all h-writes of this CTA done
        if (tid == 0) st_rel(my_flag, (unsigned)(t + 1));

        // off the critical path:
        out[oi_base + t * HH] = hnew;
        if (t + 1 < TT) xp_cur = __ldg(&out[oi_base + (t + 1) * HH]);

        int tmp = cur; cur = nxt; nxt = nnx; nnx = tmp;
    }
}

// ---------------------------------------------------------------------------
// Launch: input-projection GEMM (+ merged init) -> recurrence  (2 launches)
// ---------------------------------------------------------------------------
extern "C" void kernel_launch(void* const* d_in, const int* in_sizes, int n_in,
                              void* d_out, int out_size)
{
    const float* x   = (const float*)d_in[0];
    const float* Wih = (const float*)d_in[1];
    const float* Whh = (const float*)d_in[2];
    const float* bih = (const float*)d_in[3];
    const float* bhh = (const float*)d_in[4];
    float* out = (float*)d_out;
    (void)in_sizes; (void)n_in; (void)out_size;

    cudaFuncSetAttribute(rnn_rec_kernel,
                         cudaFuncAttributeMaxDynamicSharedMemorySize,
                         RSM_BYTES);

    dim3 g1(HH / BN, (BB * TT) / BM);   // (16, 128)
    gemm_xp_kernel<<<g1, 256>>>(x, Wih, bih, bhh, out);

    rnn_rec_kernel<<<RGRID, 256, RSM_BYTES>>>(Whh, out);
}

// round 9
// speedup vs baseline: 1.2321x; 1.0353x over previous
#include <cuda_runtime.h>

// Problem sizes (fixed by the reference)
#define BB 32
#define TT 512
#define EE 1024
#define HH 1024

// ---------------------------------------------------------------------------
// f32x2 packed-FMA helpers (sm_103a FFMA2 path; ptxas only emits via PTX)
// ---------------------------------------------------------------------------
static __device__ __forceinline__ void fma2(unsigned long long &acc,
                                            unsigned long long a,
                                            unsigned long long b) {
    asm("fma.rn.f32x2 %0, %1, %2, %0;" : "+l"(acc) : "l"(a), "l"(b));
}
static __device__ __forceinline__ float2 unpk(unsigned long long v) {
    float2 r;
    asm("mov.b64 {%0, %1}, %2;" : "=f"(r.x), "=f"(r.y) : "l"(v));
    return r;
}
static __device__ __forceinline__ unsigned ld_acq(const unsigned* p) {
    unsigned v;
    asm volatile("ld.acquire.gpu.u32 %0, [%1];" : "=r"(v) : "l"(p));
    return v;
}
static __device__ __forceinline__ void st_rel(unsigned* p, unsigned v) {
    asm volatile("st.release.gpu.u32 [%0], %1;" :: "l"(p), "r"(v) : "memory");
}
static __device__ __forceinline__ float tanh_fast(float x) {
    float y;
    asm("tanh.approx.f32 %0, %1;" : "=f"(y) : "f"(x));
    return y;
}

// ---------------------------------------------------------------------------
// Global scratch: 3-deep hidden-state ring + per-CTA monotonic step flags
// ---------------------------------------------------------------------------
__device__ float    g_h[3][BB * HH];
__device__ unsigned g_flag[128 * 32];       // one flag per CTA, 128B stride

// ---------------------------------------------------------------------------
// Phase 1: out[m][n] = sum_k X[m][k] * W[n][k] + (bih[n] + bhh[n])
// M=16384, N=1024, K=1024, NT GEMM, FFMA2, 128x64 tile, double-buffered smem.
// Block (0,0) additionally zeroes g_h[0] and the flags (init merged here).
// ---------------------------------------------------------------------------
#define BM  128
#define BN  64
#define BK  32
#define LDA 36

__global__ __launch_bounds__(256) void gemm_xp_kernel(
    const float* __restrict__ X, const float* __restrict__ W,
    const float* __restrict__ bih, const float* __restrict__ bhh,
    float* __restrict__ out)
{
    __shared__ __align__(16) float As[2][BM * LDA];
    __shared__ __align__(16) float Bs[2][BN * LDA];

    const int tid = threadIdx.x;
    const int m0  = blockIdx.y * BM;
    const int n0  = blockIdx.x * BN;
    const int r   = tid & 15;
    const int c   = tid >> 4;

    // ---- merged init (block (0,0) only): zero h_0 ring slot + flags ------
    if (blockIdx.x == 0 && blockIdx.y == 0) {
        float4 z4 = make_float4(0.f, 0.f, 0.f, 0.f);
#pragma unroll
        for (int u = 0; u < 32; u++)                    // 32K floats = 8K f4
            *((float4*)g_h[0] + tid + u * 256) = z4;
#pragma unroll
        for (int u = 0; u < 16; u++)                    // 4096 flags
            g_flag[tid + u * 256] = 0u;
    }

    // staging coordinates (same for every tile)
    const int srow = tid >> 3;
    const int skk  = (tid & 7) << 2;

    unsigned long long acc[8][4];
#pragma unroll
    for (int i = 0; i < 8; i++)
#pragma unroll
        for (int j = 0; j < 4; j++) acc[i][j] = 0ull;

    // Preload tile 0
#pragma unroll
    for (int u = 0; u < 4; u++)
        *(float4*)&As[0][(srow + u * 32) * LDA + skk] =
            *(const float4*)&X[(m0 + srow + u * 32) * EE + skk];
#pragma unroll
    for (int u = 0; u < 2; u++)
        *(float4*)&Bs[0][(srow + u * 32) * LDA + skk] =
            *(const float4*)&W[(n0 + srow + u * 32) * EE + skk];
    __syncthreads();

    int cur = 0;
    for (int kt = 0; kt < EE; kt += BK) {
        float4 pa[4], pb[2];
        if (kt + BK < EE) {
#pragma unroll
            for (int u = 0; u < 4; u++)
                pa[u] = *(const float4*)&X[(m0 + srow + u * 32) * EE + kt + BK + skk];
#pragma unroll
            for (int u = 0; u < 2; u++)
                pb[u] = *(const float4*)&W[(n0 + srow + u * 32) * EE + kt + BK + skk];
        }

#pragma unroll
        for (int kk = 0; kk < BK; kk += 4) {
            ulonglong2 av[8];
            ulonglong2 bv[4];
#pragma unroll
            for (int i = 0; i < 8; i++)
                av[i] = *(const ulonglong2*)&As[cur][(r + 16 * i) * LDA + kk];
#pragma unroll
            for (int j = 0; j < 4; j++)
                bv[j] = *(const ulonglong2*)&Bs[cur][(c + 16 * j) * LDA + kk];
#pragma unroll
            for (int i = 0; i < 8; i++) {
#pragma unroll
                for (int j = 0; j < 4; j++) {
                    fma2(acc[i][j], av[i].x, bv[j].x);
                    fma2(acc[i][j], av[i].y, bv[j].y);
                }
            }
        }

        if (kt + BK < EE) {
#pragma unroll
            for (int u = 0; u < 4; u++)
                *(float4*)&As[1 - cur][(srow + u * 32) * LDA + skk] = pa[u];
#pragma unroll
            for (int u = 0; u < 2; u++)
                *(float4*)&Bs[1 - cur][(srow + u * 32) * LDA + skk] = pb[u];
        }
        __syncthreads();
        cur ^= 1;
    }

#pragma unroll
    for (int j = 0; j < 4; j++) {
        int n = n0 + c + 16 * j;
        float bias = bih[n] + bhh[n];
#pragma unroll
        for (int i = 0; i < 8; i++) {
            float2 v = unpk(acc[i][j]);
            out[(m0 + r + 16 * i) * HH + n] = v.x + v.y + bias;
        }
    }
}

// ---------------------------------------------------------------------------
// Phase 2: persistent recurrence. 128 CTAs (co-resident), 256 threads.
//   CTA = batch group gb (8 batches) x col block cb (32 cols), full K = 1024.
//   Thread (ks = tid>>2 in 0..63, c8 = tid&3) computes an
//   8 batch x 8 col (cols c8*8..c8*8+7) x Kt=16 FFMA2 partial;
//   KS=64 partials reduced via a 64 KB smem tile.
//
//   Bank analysis (8-lane phase = 2 ks values x 4 c8):
//     W: stored with low-2 swizzle gp = (g&~3)|((g ^ (col>>3))&3); load
//        granule&7 = 4*(ks&1) + ((kq^c8)&3) -> all 8 bank-groups: CONFLICT-FREE
//     h: natural layout; load granule&7 = 4*(ks&1)+kq -> 2 distinct broadcast
//        addresses per phase: CONFLICT-FREE. Stage stores granule = 4*ks+c8:
//        &7 = 4*(ks&1)+c8 -> 8 distinct: CONFLICT-FREE.
//   Sync: per-CTA monotonic flag (release/acquire), 3-deep h ring, 4-thread
//   staging groups, NO nanosleep (plain acquire spin, warp-coalesced).
// ---------------------------------------------------------------------------
#define RGRID   128
#define RW_FLT  (32 * 1024)   // W slice, swizzled     (128 KB)
#define RH_FLT  (8 * 1024)    // h slice               ( 32 KB)
#define RR_FLT  (64 * 256)    // reduction partials    ( 64 KB)
#define RSM_BYTES ((RW_FLT + RH_FLT + RR_FLT) * 4)

__global__ __launch_bounds__(256, 1) void rnn_rec_kernel(
    const float* __restrict__ Whh, float* __restrict__ out)
{
    extern __shared__ __align__(16) float sm[];
    float* Ws  = sm;                     // [32 cols][1024] swizzled
    float* hs  = sm + RW_FLT;            // [8 batches][1024]
    float* red = sm + RW_FLT + RH_FLT;   // [64 ks][256 outputs]

    const int tid = threadIdx.x;
    const int gb  = blockIdx.x >> 5;          // batch group 0..3
    const int c0  = (blockIdx.x & 31) * 32;   // global col base
    const int ks  = tid >> 2;                 // k chunk 0..63 (16 floats)
    const int c8  = tid & 3;                  // col oct 0..3

    // ---- Stage W slice (once), low-2 swizzle keyed on col oct ------------
#pragma unroll 4
    for (int u = 0; u < 32; u++) {
        int f   = tid + u * 256;          // float4 index 0..8191
        int col = f >> 8;                 // local col 0..31
        int g   = f & 255;                // granule
        int gp  = (g & ~3) | ((g ^ (col >> 3)) & 3);
        float4 v = *(const float4*)&Whh[(c0 + col) * HH + g * 4];
        *(float4*)&Ws[col * 1024 + gp * 4] = v;
    }

    // Per-thread invariant pointers
    const float* wbase = &Ws[(c8 * 8) * 1024 + ks * 16];
    const float* hbase = &hs[ks * 16];

    // Producer of this thread's k chunk: CTA (gb, ks>>1) (32 cols/CTA)
    const unsigned* my_src_flag = &g_flag[(gb * 32 + (ks >> 1)) * 32];
    unsigned*       my_flag     = &g_flag[blockIdx.x * 32];

    // Staging: thread copies granule column (4*ks + c8) across 8 rows
    const int g_st = ks * 4 + c8;
    const unsigned grp_mask = 0xFu << (4 * (ks & 7));   // 4-lane group

    // Epilogue output mapping: o = tid = b*32 + colL (coalesced)
    const int b_out   = tid >> 5;
    const int colL    = tid & 31;
    const int oi_base = (gb * 8 + b_out) * TT * HH + (c0 + colL);
    const int hw_idx  = (gb * 8 + b_out) * HH + (c0 + colL);

    int cur = 0, nxt = 1, nnx = 2;        // rotating ring indices
    float xp_cur = __ldg(&out[oi_base]);  // prefetch xp for t = 0

    __syncthreads();   // Ws fully staged before first microloop

    for (int t = 0; t < TT; t++) {
        // ---- Wait for this chunk's producer (plain acquire spin) ---------
        if (t) {
            while (ld_acq(my_src_flag) < (unsigned)t) { }
        }
        // ---- Stage this granule column (8 rows) --------------------------
        {
            const float4* hsrc =
                (const float4*)(g_h[cur] + gb * 8 * HH) + g_st;
            float4* hdst = (float4*)&hs[g_st * 4];
#pragma unroll
            for (int u = 0; u < 8; u++)
                *(float4*)((char*)hdst + u * 4096) = __ldcg(hsrc + u * 256);
        }
        __syncwarp(grp_mask);

        // ---- 8x8 x Kt=16 FFMA2 microtile ---------------------------------
        unsigned long long acc[8][8];
#pragma unroll
        for (int i = 0; i < 8; i++)
#pragma unroll
            for (int j = 0; j < 8; j++) acc[i][j] = 0ull;

#pragma unroll
        for (int kq = 0; kq < 4; kq++) {
            ulonglong2 wv[8];
            const int wo = ((kq ^ c8) & 3) * 4;
#pragma unroll
            for (int j = 0; j < 8; j++)
                wv[j] = *(const ulonglong2*)(wbase + j * 1024 + wo);
#pragma unroll
            for (int i = 0; i < 8; i++) {
                ulonglong2 hv = *(const ulonglong2*)(hbase + i * 1024 + kq * 4);
#pragma unroll
                for (int j = 0; j < 8; j++) {
                    fma2(acc[i][j], hv.x, wv[j].x);
                    fma2(acc[i][j], hv.y, wv[j].y);
                }
            }
        }

        // ---- Reduce KS=64 partials through smem --------------------------
#pragma unroll
        for (int i = 0; i < 8; i++) {
            float2 a0 = unpk(acc[i][0]), a1 = unpk(acc[i][1]);
            float2 a2 = unpk(acc[i][2]), a3 = unpk(acc[i][3]);
            float2 a4 = unpk(acc[i][4]), a5 = unpk(acc[i][5]);
            float2 a6 = unpk(acc[i][6]), a7 = unpk(acc[i][7]);
            float4 v0, v1;
            v0.x = a0.x + a0.y; v0.y = a1.x + a1.y;
            v0.z = a2.x + a2.y; v0.w = a3.x + a3.y;
            v1.x = a4.x + a4.y; v1.y = a5.x + a5.y;
            v1.z = a6.x + a6.y; v1.w = a7.x + a7.y;
            *(float4*)&red[ks * 256 + i * 32 + c8 * 8]     = v0;
            *(float4*)&red[ks * 256 + i * 32 + c8 * 8 + 4] = v1;
        }
        __syncthreads();

        float s0 = 0.f, s1 = 0.f, s2 = 0.f, s3 = 0.f;
#pragma unroll
        for (int k = 0; k < 64; k += 4) {
            s0 += red[(k + 0) * 256 + tid];
            s1 += red[(k + 1) * 256 + tid];
            s2 += red[(k + 2) * 256 + tid];
            s3 += red[(k + 3) * 256 + tid];
        }
        float s = (s0 + s1) + (s2 + s3);

        // ---- tanh, publish h, release flag -------------------------------
        float hnew = tanh_fast(xp_cur + s);
        g_h[nxt][hw_idx] = hnew;
        __syncthreads();                 // all h-writes of this CTA done
        if (tid == 0) st_rel(my_flag, (unsigned)(t + 1));

        // off the critical path:
        out[oi_base + t * HH] = hnew;
        if (t + 1 < TT) xp_cur = __ldg(&out[oi_base + (t + 1) * HH]);

        int tmp = cur; cur = nxt; nxt = nnx; nnx = tmp;
    }
}

// ---------------------------------------------------------------------------
// Launch: input-projection GEMM (+ merged init) -> recurrence  (2 launches)
// ---------------------------------------------------------------------------
extern "C" void kernel_launch(void* const* d_in, const int* in_sizes, int n_in,
                              void* d_out, int out_size)
{
    const float* x   = (const float*)d_in[0];
    const float* Wih = (const float*)d_in[1];
    const float* Whh = (const float*)d_in[2];
    const float* bih = (const float*)d_in[3];
    const float* bhh = (const float*)d_in[4];
    float* out = (float*)d_out;
    (void)in_sizes; (void)n_in; (void)out_size;

    cudaFuncSetAttribute(rnn_rec_kernel,
                         cudaFuncAttributeMaxDynamicSharedMemorySize,
                         RSM_BYTES);

    dim3 g1(HH / BN, (BB * TT) / BM);   // (16, 128)
    gemm_xp_kernel<<<g1, 256>>>(x, Wih, bih, bhh, out);

    rnn_rec_kernel<<<RGRID, 256, RSM_BYTES>>>(Whh, out);
}